// round 13
// baseline (speedup 1.0000x reference)
#include <cuda_runtime.h>
#include <cuda_bf16.h>
#include <math.h>
#include <stdint.h>

#define T_TOK   65536
#define D_EMB   256
#define H_DIM   64
#define N_EXP   10
#define MTOK    128
#define NBLK_C  16384
#define NBLK_G  (T_TOK / 32)
#define NBLK_PX 16384       // x-split blocks in k_prep
#define NBLK_PW 320         // weight-split blocks in k_prep

// smem element strides (bf16 elems), 4-bank shift per row
#define SA1 264
#define SB1 72
#define SA2 72
#define SB2 264

// byte offsets in the 1024-aligned dynamic smem tile
#define A1HI 0
#define A1LO 67584         // 128*264*2
#define B1HI 135168
#define B1LO 172032        // +256*72*2
#define B2HI 0
#define B2LO 33792         // 64*264*2
#define A2HI 135168
#define A2LO 153600        // +128*72*2
#define ASH_OFF 208896
#define GSH_OFF 209408
#define SMEM_FFN (209920 + 1024)

// ---------------- scratch ------------------------------------------------------
__device__ int      g_count[N_EXP];
__device__ int      g_bucket[N_EXP * T_TOK];
__device__ float    g_gates[T_TOK * 2];
__device__ float    g_part [(size_t)T_TOK * 2 * D_EMB];
__device__ float    g_kd_part[NBLK_C];
__device__ float    g_imp_part[NBLK_G * N_EXP];
__device__ uint32_t g_xhi[(size_t)T_TOK * 128];      // bf16x2-packed x hi
__device__ uint32_t g_xlo[(size_t)T_TOK * 128];      // bf16x2-packed x lo
__device__ uint32_t g_w1hi[N_EXP * 8192];            // w1 [e][k=256][n=64]
__device__ uint32_t g_w1lo[N_EXP * 8192];
__device__ uint32_t g_w2hi[N_EXP * 8192];            // w2 [e][k=64][n=256]
__device__ uint32_t g_w2lo[N_EXP * 8192];

// ---------------- helpers --------------------------------------------------------
__device__ __forceinline__ uint32_t smem_u32(const void* p) {
    uint32_t a;
    asm("{ .reg .u64 t; cvta.to.shared.u64 t, %1; cvt.u32.u64 %0, t; }" : "=r"(a) : "l"(p));
    return a;
}
__device__ __forceinline__ uint32_t bf16x2_rn(float lo, float hi) {
    uint32_t r;
    asm("cvt.rn.bf16x2.f32 %0,%1,%2;" : "=r"(r) : "f"(hi), "f"(lo));
    return r;
}
__device__ __forceinline__ void split2(float f0, float f1, uint32_t& hp, uint32_t& lp) {
    hp = bf16x2_rn(f0, f1);
    float r0 = f0 - __uint_as_float(hp << 16);
    float r1 = f1 - __uint_as_float(hp & 0xFFFF0000u);
    lp = bf16x2_rn(r0, r1);
}
__device__ __forceinline__ void sts32(uint32_t addr, uint32_t v) {
    asm volatile("st.shared.b32 [%0], %1;" :: "r"(addr), "r"(v) : "memory");
}
__device__ __forceinline__ void sts128(uint32_t addr, uint4 v) {
    asm volatile("st.shared.v4.b32 [%0], {%1,%2,%3,%4};"
                 :: "r"(addr), "r"(v.x), "r"(v.y), "r"(v.z), "r"(v.w) : "memory");
}
__device__ __forceinline__ void ldm4(uint32_t* r, uint32_t a) {
    asm volatile("ldmatrix.sync.aligned.m8n8.x4.shared.b16 {%0,%1,%2,%3}, [%4];"
                 : "=r"(r[0]), "=r"(r[1]), "=r"(r[2]), "=r"(r[3]) : "r"(a));
}
__device__ __forceinline__ void ldm4t(uint32_t* r, uint32_t a) {
    asm volatile("ldmatrix.sync.aligned.m8n8.x4.trans.shared.b16 {%0,%1,%2,%3}, [%4];"
                 : "=r"(r[0]), "=r"(r[1]), "=r"(r[2]), "=r"(r[3]) : "r"(a));
}
__device__ __forceinline__ void mma_bf16(float* c, const uint32_t* a, uint32_t b0, uint32_t b1) {
    asm volatile(
        "mma.sync.aligned.m16n8k16.row.col.f32.bf16.bf16.f32 "
        "{%0,%1,%2,%3},{%4,%5,%6,%7},{%8,%9},{%0,%1,%2,%3};"
        : "+f"(c[0]), "+f"(c[1]), "+f"(c[2]), "+f"(c[3])
        : "r"(a[0]), "r"(a[1]), "r"(a[2]), "r"(a[3]), "r"(b0), "r"(b1));
}

// ---------------- kernel P: pre-split x and weights into bf16 hi/lo ------------
__global__ void __launch_bounds__(256) k_prep(const float* __restrict__ x,
                                              const float* __restrict__ w1,
                                              const float* __restrict__ w2) {
    int b = blockIdx.x;
    if (b < NBLK_PX) {
        size_t i = (size_t)b * 256 + threadIdx.x;       // float4 index over x
        float4 v = ((const float4*)x)[i];
        uint32_t h0, l0, h1, l1;
        split2(v.x, v.y, h0, l0);
        split2(v.z, v.w, h1, l1);
        ((uint2*)g_xhi)[i] = make_uint2(h0, h1);
        ((uint2*)g_xlo)[i] = make_uint2(l0, l1);
    } else {
        int i = (b - NBLK_PX) * 256 + threadIdx.x;      // 0..81919
        if (i < 40960) {
            float4 v = ((const float4*)w1)[i];
            uint32_t h0, l0, h1, l1;
            split2(v.x, v.y, h0, l0);
            split2(v.z, v.w, h1, l1);
            ((uint2*)g_w1hi)[i] = make_uint2(h0, h1);
            ((uint2*)g_w1lo)[i] = make_uint2(l0, l1);
        } else {
            int j = i - 40960;
            float4 v = ((const float4*)w2)[j];
            uint32_t h0, l0, h1, l1;
            split2(v.x, v.y, h0, l0);
            split2(v.z, v.w, h1, l1);
            ((uint2*)g_w2hi)[j] = make_uint2(h0, h1);
            ((uint2*)g_w2lo)[j] = make_uint2(l0, l1);
        }
    }
}

// ---------------- kernel A: gating + importance partials (proven) ---------------
__global__ void __launch_bounds__(256) k_gate(const float* __restrict__ x,
                                              const float* __restrict__ wg) {
    __shared__ float wgs[N_EXP * D_EMB];
    __shared__ float impW[8][N_EXP];
    int tid = threadIdx.x;
    for (int i = tid; i < D_EMB * N_EXP; i += 256) {
        int e = i / D_EMB, d = i - e * D_EMB;
        wgs[i] = wg[d * N_EXP + e];
    }
    __syncthreads();

    int warp = tid >> 5, lane = tid & 31;
    int t0 = blockIdx.x * 32 + warp * 4;

    float impL[N_EXP];
#pragma unroll
    for (int e = 0; e < N_EXP; ++e) impL[e] = 0.f;

    for (int r = 0; r < 4; ++r) {
        int t = t0 + r;
        float part[N_EXP];
#pragma unroll
        for (int e = 0; e < N_EXP; ++e) part[e] = 0.f;
#pragma unroll
        for (int dd = 0; dd < 8; ++dd) {
            int d = dd * 32 + lane;
            float xv = x[(size_t)t * D_EMB + d];
#pragma unroll
            for (int e = 0; e < N_EXP; ++e)
                part[e] = fmaf(xv, wgs[e * D_EMB + d], part[e]);
        }
#pragma unroll
        for (int e = 0; e < N_EXP; ++e) {
#pragma unroll
            for (int off = 16; off; off >>= 1)
                part[e] += __shfl_xor_sync(0xffffffffu, part[e], off);
        }
        if (lane == 0) {
            float m0 = -1e30f; int e0 = 0;
#pragma unroll
            for (int e = 0; e < N_EXP; ++e) if (part[e] > m0) { m0 = part[e]; e0 = e; }
            float m1 = -1e30f; int e1 = 0;
#pragma unroll
            for (int e = 0; e < N_EXP; ++e) if (e != e0 && part[e] > m1) { m1 = part[e]; e1 = e; }
            float ex = expf(m1 - m0);
            float s  = 1.f + ex;
            float g0 = 1.f / s;
            float g1 = ex / s;
            g_gates[2 * t]     = g0;
            g_gates[2 * t + 1] = g1;
#pragma unroll
            for (int q = 0; q < N_EXP; ++q) {
                if (q == e0) impL[q] += g0;
                if (q == e1) impL[q] += g1;
            }
            int p0 = atomicAdd(&g_count[e0], 1);
            g_bucket[e0 * T_TOK + p0] = (t << 1);
            int p1 = atomicAdd(&g_count[e1], 1);
            g_bucket[e1 * T_TOK + p1] = (t << 1) | 1;
        }
    }

    if (lane == 0) {
#pragma unroll
        for (int e = 0; e < N_EXP; ++e) impW[warp][e] = impL[e];
    }
    __syncthreads();
    if (tid < N_EXP) {
        float s = 0.f;
#pragma unroll
        for (int w = 0; w < 8; ++w) s += impW[w][tid];
        g_imp_part[blockIdx.x * N_EXP + tid] = s;
    }
}

// ---------------- kernel B: mma.sync split-bf16 FFN (copy-only staging) ---------
__global__ void __launch_bounds__(256, 1) k_ffn(const float* __restrict__ b1,
                                                const float* __restrict__ b2) {
    int e = blockIdx.y;
    int n_total = g_count[e];
    int base = blockIdx.x * MTOK;
    if (base >= n_total) return;

    extern __shared__ char smraw[];
    char* bp = (char*)(((uintptr_t)smraw + 1023) & ~(uintptr_t)1023);
    uint32_t tb = smem_u32(bp);
    int*   ash = (int*)(bp + ASH_OFF);
    float* gsh = (float*)(bp + GSH_OFF);

    int tid  = threadIdx.x;
    int lane = tid & 31;
    int R    = (tid >> 5) * 16;

    if (tid < MTOK) {
        int a = (base + tid < n_total) ? g_bucket[e * T_TOK + base + tid] : -1;
        ash[tid] = a;
        gsh[tid] = (a >= 0) ? g_gates[a] : 0.f;
    }
    __syncthreads();

    // ---- stage A1: copy pre-split bf16 rows (row tid>>1, half tid&1) ----
    {
        int row  = tid >> 1;
        int half = tid & 1;
        int a = ash[row];
        const uint4* sh = (a >= 0) ? (const uint4*)(g_xhi + (size_t)(a >> 1) * 128 + half * 64)
                                   : (const uint4*)0;
        const uint4* sl = (a >= 0) ? (const uint4*)(g_xlo + (size_t)(a >> 1) * 128 + half * 64)
                                   : (const uint4*)0;
        uint32_t dst = tb + A1HI + (uint32_t)row * (SA1 * 2) + half * 256;
        uint4 z = make_uint4(0, 0, 0, 0);
#pragma unroll 4
        for (int i = 0; i < 16; ++i) {
            sts128(dst + i * 16,                 (a >= 0) ? sh[i] : z);
            sts128(dst + i * 16 + (A1LO - A1HI), (a >= 0) ? sl[i] : z);
        }
    }

    // ---- stage B1: copy pre-split w1 (k-row = 8 uint4) ----
    {
        const uint4* wh = (const uint4*)(g_w1hi + e * 8192);
        const uint4* wl = (const uint4*)(g_w1lo + e * 8192);
#pragma unroll 4
        for (int i = tid; i < 2048; i += 256) {
            int k = i >> 3;
            uint32_t dst = tb + B1HI + (uint32_t)k * (SB1 * 2) + (i & 7) * 16;
            sts128(dst,                 wh[i]);
            sts128(dst + (B1LO - B1HI), wl[i]);
        }
    }
    __syncthreads();

    int rowA = R + (lane & 7) + ((lane >> 3) & 1) * 8;
    int kAo  = (lane >> 4) * 8;
    int kBo  = (lane & 7) + ((lane >> 3) & 1) * 8;
    int nBo  = (lane >> 4) * 8;

    // ---- GEMM1 ----
    float acc1[8][4];
#pragma unroll
    for (int j = 0; j < 8; ++j)
#pragma unroll
        for (int q = 0; q < 4; ++q) acc1[j][q] = 0.f;

#pragma unroll 2
    for (int s = 0; s < 16; ++s) {
        uint32_t ah[4], al[4];
        uint32_t aAddr = tb + A1HI + ((uint32_t)(rowA * SA1 + s * 16 + kAo) << 1);
        ldm4(ah, aAddr);
        ldm4(al, aAddr + (A1LO - A1HI));
#pragma unroll
        for (int jp = 0; jp < 4; ++jp) {
            uint32_t bh[4], bl[4];
            uint32_t bAddr = tb + B1HI + ((uint32_t)((s * 16 + kBo) * SB1 + jp * 16 + nBo) << 1);
            ldm4t(bh, bAddr);
            ldm4t(bl, bAddr + (B1LO - B1HI));
            mma_bf16(acc1[2 * jp],     ah, bh[0], bh[1]);
            mma_bf16(acc1[2 * jp],     ah, bl[0], bl[1]);
            mma_bf16(acc1[2 * jp],     al, bh[0], bh[1]);
            mma_bf16(acc1[2 * jp + 1], ah, bh[2], bh[3]);
            mma_bf16(acc1[2 * jp + 1], ah, bl[2], bl[3]);
            mma_bf16(acc1[2 * jp + 1], al, bh[2], bh[3]);
        }
    }
    __syncthreads();

    // ---- epilogue1: h = relu(D1 + b1) -> A2 (split, data-dependent) ----
    {
        int g = lane >> 2, t = lane & 3;
        int r0 = R + g, r1 = R + g + 8;
#pragma unroll
        for (int j = 0; j < 8; ++j) {
            int h0 = 8 * j + 2 * t;
            float2 bv = *(const float2*)(b1 + e * H_DIM + h0);
            float v0 = fmaxf(acc1[j][0] + bv.x, 0.f);
            float v1 = fmaxf(acc1[j][1] + bv.y, 0.f);
            float v2 = fmaxf(acc1[j][2] + bv.x, 0.f);
            float v3 = fmaxf(acc1[j][3] + bv.y, 0.f);
            uint32_t hp, lp;
            split2(v0, v1, hp, lp);
            uint32_t d0 = tb + A2HI + ((uint32_t)(r0 * SA2 + h0) << 1);
            sts32(d0, hp);
            sts32(d0 + (A2LO - A2HI), lp);
            split2(v2, v3, hp, lp);
            uint32_t d1 = tb + A2HI + ((uint32_t)(r1 * SA2 + h0) << 1);
            sts32(d1, hp);
            sts32(d1 + (A2LO - A2HI), lp);
        }
    }

    // ---- stage B2: copy pre-split w2 (k-row = 32 uint4) ----
    {
        const uint4* wh = (const uint4*)(g_w2hi + e * 8192);
        const uint4* wl = (const uint4*)(g_w2lo + e * 8192);
#pragma unroll 4
        for (int i = tid; i < 2048; i += 256) {
            int k = i >> 5;
            uint32_t dst = tb + B2HI + (uint32_t)k * (SB2 * 2) + (i & 31) * 16;
            sts128(dst,                 wh[i]);
            sts128(dst + (B2LO - B2HI), wl[i]);
        }
    }
    __syncthreads();

    // ---- GEMM2 ----
    uint32_t ah2[4][4], al2[4][4];
#pragma unroll
    for (int s = 0; s < 4; ++s) {
        uint32_t aAddr = tb + A2HI + ((uint32_t)(rowA * SA2 + s * 16 + kAo) << 1);
        ldm4(ah2[s], aAddr);
        ldm4(al2[s], aAddr + (A2LO - A2HI));
    }

    int g = lane >> 2, t = lane & 3;
    int aR0 = ash[R + g], aR1 = ash[R + g + 8];
    float gv0 = gsh[R + g], gv1 = gsh[R + g + 8];

#pragma unroll 1
    for (int c = 0; c < 4; ++c) {
        float acc2[8][4];
#pragma unroll
        for (int j = 0; j < 8; ++j)
#pragma unroll
            for (int q = 0; q < 4; ++q) acc2[j][q] = 0.f;

#pragma unroll
        for (int s = 0; s < 4; ++s) {
#pragma unroll
            for (int jp = 0; jp < 4; ++jp) {
                uint32_t bh[4], bl[4];
                uint32_t bAddr = tb + B2HI +
                    ((uint32_t)((s * 16 + kBo) * SB2 + c * 64 + jp * 16 + nBo) << 1);
                ldm4t(bh, bAddr);
                ldm4t(bl, bAddr + (B2LO - B2HI));
                mma_bf16(acc2[2 * jp],     ah2[s], bh[0], bh[1]);
                mma_bf16(acc2[2 * jp],     ah2[s], bl[0], bl[1]);
                mma_bf16(acc2[2 * jp],     al2[s], bh[0], bh[1]);
                mma_bf16(acc2[2 * jp + 1], ah2[s], bh[2], bh[3]);
                mma_bf16(acc2[2 * jp + 1], ah2[s], bl[2], bl[3]);
                mma_bf16(acc2[2 * jp + 1], al2[s], bh[2], bh[3]);
            }
        }

#pragma unroll
        for (int j = 0; j < 8; ++j) {
            int o0 = c * 64 + 8 * j + 2 * t;
            float2 bv = *(const float2*)(b2 + e * D_EMB + o0);
            if (aR0 >= 0) {
                float2 o;
                o.x = (acc2[j][0] + bv.x) * gv0;
                o.y = (acc2[j][1] + bv.y) * gv0;
                *(float2*)(g_part + (size_t)aR0 * D_EMB + o0) = o;
            }
            if (aR1 >= 0) {
                float2 o;
                o.x = (acc2[j][2] + bv.x) * gv1;
                o.y = (acc2[j][3] + bv.y) * gv1;
                *(float2*)(g_part + (size_t)aR1 * D_EMB + o0) = o;
            }
        }
    }
}

// ---------------- kernel C: combine (proven) -------------------------------------
__global__ void __launch_bounds__(256) k_combine(float* __restrict__ out) {
    __shared__ float red[256];
    int tid = threadIdx.x;
    size_t f4 = (size_t)blockIdx.x * 256 + tid;
    size_t t  = f4 >> 6;
    int    q  = (int)(f4 & 63);

    float4 aa = *((const float4*)(g_part + (t * 2)     * D_EMB) + q);
    float4 bb = *((const float4*)(g_part + (t * 2 + 1) * D_EMB) + q);
    float4 y;
    y.x = aa.x + bb.x; y.y = aa.y + bb.y; y.z = aa.z + bb.z; y.w = aa.w + bb.w;

    float kd = fabsf(y.x) + fabsf(y.y) + fabsf(y.z) + fabsf(y.w);

    float4 o;
    o.x = y.x * 0.5f; o.y = y.y * 0.5f; o.z = y.z * 0.5f; o.w = y.w * 0.5f;
    ((float4*)out)[f4] = o;

    red[tid] = kd;
    __syncthreads();
    for (int s = 128; s; s >>= 1) {
        if (tid < s) red[tid] += red[tid + s];
        __syncthreads();
    }
    if (tid == 0) g_kd_part[blockIdx.x] = red[0];
}

// ---------------- kernel D: finalize loss + reset counters (proven) --------------
__global__ void __launch_bounds__(256) k_final(float* __restrict__ out, int out_size) {
    __shared__ float red[256];
    __shared__ float impS[N_EXP * 256];
    int tid = threadIdx.x;

    float s = 0.f;
    for (int i = tid; i < NBLK_C; i += 256) s += g_kd_part[i];
    red[tid] = s;
    __syncthreads();
    for (int st = 128; st; st >>= 1) {
        if (tid < st) red[tid] += red[tid + st];
        __syncthreads();
    }
    float kd_total = red[0];
    __syncthreads();

    float imp[N_EXP];
#pragma unroll
    for (int e = 0; e < N_EXP; ++e) imp[e] = 0.f;
    for (int i = tid; i < NBLK_G; i += 256) {
#pragma unroll
        for (int e = 0; e < N_EXP; ++e)
            imp[e] += g_imp_part[i * N_EXP + e];
    }
#pragma unroll
    for (int e = 0; e < N_EXP; ++e) impS[e * 256 + tid] = imp[e];
    __syncthreads();
    for (int st = 128; st; st >>= 1) {
        if (tid < st)
#pragma unroll
            for (int e = 0; e < N_EXP; ++e)
                impS[e * 256 + tid] += impS[e * 256 + tid + st];
        __syncthreads();
    }

    if (tid == 0) {
        float iv[N_EXP], lv[N_EXP];
        float si = 0.f, sl = 0.f;
#pragma unroll
        for (int e = 0; e < N_EXP; ++e) {
            iv[e] = impS[e * 256];
            lv[e] = (float)g_count[e];
            si += iv[e]; sl += lv[e];
        }
        float mi = si / (float)N_EXP, ml = sl / (float)N_EXP;
        float vi = 0.f, vl = 0.f;
#pragma unroll
        for (int e = 0; e < N_EXP; ++e) {
            float di = iv[e] - mi; vi += di * di;
            float dl = lv[e] - ml; vl += dl * dl;
        }
        vi /= (float)(N_EXP - 1);
        vl /= (float)(N_EXP - 1);
        float aux = vi / (mi * mi + 1e-10f) + vl / (ml * ml + 1e-10f);
        float kd  = kd_total / (float)((size_t)T_TOK * D_EMB);
        if (out_size > T_TOK * D_EMB)
            out[(size_t)T_TOK * D_EMB] = aux + kd;
    }

    __syncthreads();
    if (tid < N_EXP) g_count[tid] = 0;
}

// ---------------- launch ----------------------------------------------------------
extern "C" void kernel_launch(void* const* d_in, const int* in_sizes, int n_in,
                              void* d_out, int out_size) {
    const float* x  = (const float*)d_in[0];
    const float* wg = (const float*)d_in[1];
    const float* w1 = (const float*)d_in[2];
    const float* b1 = (const float*)d_in[3];
    const float* w2 = (const float*)d_in[4];
    const float* b2 = (const float*)d_in[5];
    float* out = (float*)d_out;

    cudaFuncSetAttribute(k_ffn, cudaFuncAttributeMaxDynamicSharedMemorySize, SMEM_FFN);

    k_prep<<<NBLK_PX + NBLK_PW, 256>>>(x, w1, w2);
    k_gate<<<NBLK_G, 256>>>(x, wg);
    dim3 gB(T_TOK / MTOK, N_EXP);
    k_ffn<<<gB, 256, SMEM_FFN>>>(b1, b2);
    k_combine<<<NBLK_C, 256>>>(out);
    k_final<<<1, 256>>>(out, out_size);
}

// round 15
// speedup vs baseline: 1.1699x; 1.1699x over previous
#include <cuda_runtime.h>
#include <cuda_bf16.h>
#include <math.h>
#include <stdint.h>

#define T_TOK   65536
#define D_EMB   256
#define H_DIM   64
#define N_EXP   10
#define MTOK    128
#define NBLK_C  16384
#define NBLK_G  (T_TOK / 32)

// smem element strides (bf16 elems), 4-bank shift per row
#define SA1 136            // 128 k-chunk + 8 pad
#define SB1 72
#define SA2 72
#define SB2 264

// byte offsets in the 1024-aligned dynamic smem tile
// phase 1 (per k-chunk):
#define A1HI 0
#define A1LO 34816         // 128*136*2
#define B1HI 69632
#define B1LO 88064         // +128*72*2
// phase 2 (reuses phase-1 space):
#define A2HI 0
#define A2LO 18432         // 128*72*2
#define B2HI 36864
#define B2LO 70656         // +64*264*2
#define ASH_OFF 106496
#define GSH_OFF 107008
#define SMEM_FFN (107520 + 1024)

// ---------------- scratch ------------------------------------------------------
__device__ int   g_count[N_EXP];
__device__ int   g_bucket[N_EXP * T_TOK];
__device__ float g_gates[T_TOK * 2];
__device__ float g_part [(size_t)T_TOK * 2 * D_EMB];
__device__ float g_kd_part[NBLK_C];
__device__ float g_imp_part[NBLK_G * N_EXP];

// ---------------- helpers --------------------------------------------------------
__device__ __forceinline__ uint32_t smem_u32(const void* p) {
    uint32_t a;
    asm("{ .reg .u64 t; cvta.to.shared.u64 t, %1; cvt.u32.u64 %0, t; }" : "=r"(a) : "l"(p));
    return a;
}
__device__ __forceinline__ uint32_t bf16x2_rn(float lo, float hi) {
    uint32_t r;
    asm("cvt.rn.bf16x2.f32 %0,%1,%2;" : "=r"(r) : "f"(hi), "f"(lo));
    return r;
}
__device__ __forceinline__ void split2(float f0, float f1, uint32_t& hp, uint32_t& lp) {
    hp = bf16x2_rn(f0, f1);
    float r0 = f0 - __uint_as_float(hp << 16);
    float r1 = f1 - __uint_as_float(hp & 0xFFFF0000u);
    lp = bf16x2_rn(r0, r1);
}
__device__ __forceinline__ void sts64(uint32_t addr, uint32_t a, uint32_t b) {
    asm volatile("st.shared.v2.b32 [%0], {%1,%2};" :: "r"(addr), "r"(a), "r"(b) : "memory");
}
__device__ __forceinline__ void sts32(uint32_t addr, uint32_t v) {
    asm volatile("st.shared.b32 [%0], %1;" :: "r"(addr), "r"(v) : "memory");
}
__device__ __forceinline__ void ldm4(uint32_t* r, uint32_t a) {
    asm volatile("ldmatrix.sync.aligned.m8n8.x4.shared.b16 {%0,%1,%2,%3}, [%4];"
                 : "=r"(r[0]), "=r"(r[1]), "=r"(r[2]), "=r"(r[3]) : "r"(a));
}
__device__ __forceinline__ void ldm4t(uint32_t* r, uint32_t a) {
    asm volatile("ldmatrix.sync.aligned.m8n8.x4.trans.shared.b16 {%0,%1,%2,%3}, [%4];"
                 : "=r"(r[0]), "=r"(r[1]), "=r"(r[2]), "=r"(r[3]) : "r"(a));
}
__device__ __forceinline__ void mma_bf16(float* c, const uint32_t* a, uint32_t b0, uint32_t b1) {
    asm volatile(
        "mma.sync.aligned.m16n8k16.row.col.f32.bf16.bf16.f32 "
        "{%0,%1,%2,%3},{%4,%5,%6,%7},{%8,%9},{%0,%1,%2,%3};"
        : "+f"(c[0]), "+f"(c[1]), "+f"(c[2]), "+f"(c[3])
        : "r"(a[0]), "r"(a[1]), "r"(a[2]), "r"(a[3]), "r"(b0), "r"(b1));
}

// ---------------- kernel A: gating + importance partials (proven) ---------------
__global__ void __launch_bounds__(256) k_gate(const float* __restrict__ x,
                                              const float* __restrict__ wg) {
    __shared__ float wgs[N_EXP * D_EMB];
    __shared__ float impW[8][N_EXP];
    int tid = threadIdx.x;
    for (int i = tid; i < D_EMB * N_EXP; i += 256) {
        int e = i / D_EMB, d = i - e * D_EMB;
        wgs[i] = wg[d * N_EXP + e];
    }
    __syncthreads();

    int warp = tid >> 5, lane = tid & 31;
    int t0 = blockIdx.x * 32 + warp * 4;

    float impL[N_EXP];
#pragma unroll
    for (int e = 0; e < N_EXP; ++e) impL[e] = 0.f;

    for (int r = 0; r < 4; ++r) {
        int t = t0 + r;
        float part[N_EXP];
#pragma unroll
        for (int e = 0; e < N_EXP; ++e) part[e] = 0.f;
#pragma unroll
        for (int dd = 0; dd < 8; ++dd) {
            int d = dd * 32 + lane;
            float xv = x[(size_t)t * D_EMB + d];
#pragma unroll
            for (int e = 0; e < N_EXP; ++e)
                part[e] = fmaf(xv, wgs[e * D_EMB + d], part[e]);
        }
#pragma unroll
        for (int e = 0; e < N_EXP; ++e) {
#pragma unroll
            for (int off = 16; off; off >>= 1)
                part[e] += __shfl_xor_sync(0xffffffffu, part[e], off);
        }
        if (lane == 0) {
            float m0 = -1e30f; int e0 = 0;
#pragma unroll
            for (int e = 0; e < N_EXP; ++e) if (part[e] > m0) { m0 = part[e]; e0 = e; }
            float m1 = -1e30f; int e1 = 0;
#pragma unroll
            for (int e = 0; e < N_EXP; ++e) if (e != e0 && part[e] > m1) { m1 = part[e]; e1 = e; }
            float ex = expf(m1 - m0);
            float s  = 1.f + ex;
            float g0 = 1.f / s;
            float g1 = ex / s;
            g_gates[2 * t]     = g0;
            g_gates[2 * t + 1] = g1;
#pragma unroll
            for (int q = 0; q < N_EXP; ++q) {
                if (q == e0) impL[q] += g0;
                if (q == e1) impL[q] += g1;
            }
            int p0 = atomicAdd(&g_count[e0], 1);
            g_bucket[e0 * T_TOK + p0] = (t << 1);
            int p1 = atomicAdd(&g_count[e1], 1);
            g_bucket[e1 * T_TOK + p1] = (t << 1) | 1;
        }
    }

    if (lane == 0) {
#pragma unroll
        for (int e = 0; e < N_EXP; ++e) impW[warp][e] = impL[e];
    }
    __syncthreads();
    if (tid < N_EXP) {
        float s = 0.f;
#pragma unroll
        for (int w = 0; w < 8; ++w) s += impW[w][tid];
        g_imp_part[blockIdx.x * N_EXP + tid] = s;
    }
}

// ---------------- kernel B: mma.sync split-bf16 FFN, K-chunked, 2 blocks/SM -----
__global__ void __launch_bounds__(256, 2) k_ffn(const float* __restrict__ x,
                                                const float* __restrict__ w1,
                                                const float* __restrict__ b1,
                                                const float* __restrict__ w2,
                                                const float* __restrict__ b2) {
    int e = blockIdx.y;
    int n_total = g_count[e];
    int base = blockIdx.x * MTOK;
    if (base >= n_total) return;

    extern __shared__ char smraw[];
    char* bp = (char*)(((uintptr_t)smraw + 1023) & ~(uintptr_t)1023);
    uint32_t tb = smem_u32(bp);
    int*   ash = (int*)(bp + ASH_OFF);
    float* gsh = (float*)(bp + GSH_OFF);

    int tid  = threadIdx.x;
    int lane = tid & 31;
    int R    = (tid >> 5) * 16;

    if (tid < MTOK) {
        int a = (base + tid < n_total) ? g_bucket[e * T_TOK + base + tid] : -1;
        ash[tid] = a;
        gsh[tid] = (a >= 0) ? g_gates[a] : 0.f;
    }
    __syncthreads();

    // ldmatrix lane geometry
    int rowA = R + (lane & 7) + ((lane >> 3) & 1) * 8;
    int kAo  = (lane >> 4) * 8;
    int kBo  = (lane & 7) + ((lane >> 3) & 1) * 8;
    int nBo  = (lane >> 4) * 8;

    int srow  = tid >> 1;       // staging: token row
    int shalf = tid & 1;        // staging: k half (64 floats)
    int aS = ash[srow];
    const float* xrow = (aS >= 0) ? (x + (size_t)(aS >> 1) * D_EMB) : (const float*)0;

    float acc1[8][4];
#pragma unroll
    for (int j = 0; j < 8; ++j)
#pragma unroll
        for (int q = 0; q < 4; ++q) acc1[j][q] = 0.f;

    // ---- GEMM1 over two K=128 chunks ----
#pragma unroll 1
    for (int kc = 0; kc < 2; ++kc) {
        if (kc) __syncthreads();   // previous chunk fully consumed

        // stage A1 chunk: rows of x[k = kc*128 + shalf*64 .. +64)
        {
            const float4* src = (aS >= 0)
                ? (const float4*)(xrow + kc * 128 + shalf * 64) : (const float4*)0;
            uint32_t dst = tb + A1HI + ((uint32_t)(srow * SA1 + shalf * 64) << 1);
#pragma unroll 4
            for (int i = 0; i < 16; ++i) {
                float4 v = (aS >= 0) ? src[i] : make_float4(0.f, 0.f, 0.f, 0.f);
                uint32_t h0, l0, h1, l1;
                split2(v.x, v.y, h0, l0);
                split2(v.z, v.w, h1, l1);
                sts64(dst + i * 8,                 h0, h1);
                sts64(dst + i * 8 + (A1LO - A1HI), l0, l1);
            }
        }
        // stage B1 chunk: w1[k = kc*128 .. +128)[n=64]
        {
            const float4* w1g = (const float4*)(w1 + (size_t)e * D_EMB * H_DIM
                                                + (size_t)kc * 128 * H_DIM);
#pragma unroll 4
            for (int i = tid; i < 2048; i += 256) {
                int k  = i >> 4;
                int n4 = (i & 15) * 4;
                float4 v = w1g[i];
                uint32_t h0, l0, h1, l1;
                split2(v.x, v.y, h0, l0);
                split2(v.z, v.w, h1, l1);
                uint32_t dst = tb + B1HI + ((uint32_t)(k * SB1 + n4) << 1);
                sts64(dst,                 h0, h1);
                sts64(dst + (B1LO - B1HI), l0, l1);
            }
        }
        __syncthreads();

#pragma unroll 2
        for (int s = 0; s < 8; ++s) {
            uint32_t ah[4], al[4];
            uint32_t aAddr = tb + A1HI + ((uint32_t)(rowA * SA1 + s * 16 + kAo) << 1);
            ldm4(ah, aAddr);
            ldm4(al, aAddr + (A1LO - A1HI));
#pragma unroll
            for (int jp = 0; jp < 4; ++jp) {
                uint32_t bh[4], bl[4];
                uint32_t bAddr = tb + B1HI +
                    ((uint32_t)((s * 16 + kBo) * SB1 + jp * 16 + nBo) << 1);
                ldm4t(bh, bAddr);
                ldm4t(bl, bAddr + (B1LO - B1HI));
                mma_bf16(acc1[2 * jp],     ah, bh[0], bh[1]);
                mma_bf16(acc1[2 * jp],     ah, bl[0], bl[1]);
                mma_bf16(acc1[2 * jp],     al, bh[0], bh[1]);
                mma_bf16(acc1[2 * jp + 1], ah, bh[2], bh[3]);
                mma_bf16(acc1[2 * jp + 1], ah, bl[2], bl[3]);
                mma_bf16(acc1[2 * jp + 1], al, bh[2], bh[3]);
            }
        }
    }
    __syncthreads();   // GEMM1 reads done; smem reused for phase 2

    // ---- epilogue1: h = relu(D1 + b1) -> A2 (split bf16) ----
    {
        int g = lane >> 2, t = lane & 3;
        int r0 = R + g, r1 = R + g + 8;
#pragma unroll
        for (int j = 0; j < 8; ++j) {
            int h0 = 8 * j + 2 * t;
            float2 bv = *(const float2*)(b1 + e * H_DIM + h0);
            float v0 = fmaxf(acc1[j][0] + bv.x, 0.f);
            float v1 = fmaxf(acc1[j][1] + bv.y, 0.f);
            float v2 = fmaxf(acc1[j][2] + bv.x, 0.f);
            float v3 = fmaxf(acc1[j][3] + bv.y, 0.f);
            uint32_t hp, lp;
            split2(v0, v1, hp, lp);
            uint32_t d0 = tb + A2HI + ((uint32_t)(r0 * SA2 + h0) << 1);
            sts32(d0, hp);
            sts32(d0 + (A2LO - A2HI), lp);
            split2(v2, v3, hp, lp);
            uint32_t d1 = tb + A2HI + ((uint32_t)(r1 * SA2 + h0) << 1);
            sts32(d1, hp);
            sts32(d1 + (A2LO - A2HI), lp);
        }
    }

    // ---- stage B2 = w2[e] as [k=64][n=256] ----
    {
        const float4* w2g = (const float4*)(w2 + (size_t)e * H_DIM * D_EMB);
#pragma unroll 4
        for (int i = tid; i < 4096; i += 256) {
            int k  = i >> 6;
            int o4 = (i & 63) * 4;
            float4 v = w2g[i];
            uint32_t h0, l0, h1, l1;
            split2(v.x, v.y, h0, l0);
            split2(v.z, v.w, h1, l1);
            uint32_t dst = tb + B2HI + ((uint32_t)(k * SB2 + o4) << 1);
            sts64(dst,                 h0, h1);
            sts64(dst + (B2LO - B2HI), l0, l1);
        }
    }
    __syncthreads();

    // ---- GEMM2 ----
    uint32_t ah2[4][4], al2[4][4];
#pragma unroll
    for (int s = 0; s < 4; ++s) {
        uint32_t aAddr = tb + A2HI + ((uint32_t)(rowA * SA2 + s * 16 + kAo) << 1);
        ldm4(ah2[s], aAddr);
        ldm4(al2[s], aAddr + (A2LO - A2HI));
    }

    int g = lane >> 2, t = lane & 3;
    int aR0 = ash[R + g], aR1 = ash[R + g + 8];
    float gv0 = gsh[R + g], gv1 = gsh[R + g + 8];

#pragma unroll 1
    for (int c = 0; c < 4; ++c) {
        float acc2[8][4];
#pragma unroll
        for (int j = 0; j < 8; ++j)
#pragma unroll
            for (int q = 0; q < 4; ++q) acc2[j][q] = 0.f;

#pragma unroll
        for (int s = 0; s < 4; ++s) {
#pragma unroll
            for (int jp = 0; jp < 4; ++jp) {
                uint32_t bh[4], bl[4];
                uint32_t bAddr = tb + B2HI +
                    ((uint32_t)((s * 16 + kBo) * SB2 + c * 64 + jp * 16 + nBo) << 1);
                ldm4t(bh, bAddr);
                ldm4t(bl, bAddr + (B2LO - B2HI));
                mma_bf16(acc2[2 * jp],     ah2[s], bh[0], bh[1]);
                mma_bf16(acc2[2 * jp],     ah2[s], bl[0], bl[1]);
                mma_bf16(acc2[2 * jp],     al2[s], bh[0], bh[1]);
                mma_bf16(acc2[2 * jp + 1], ah2[s], bh[2], bh[3]);
                mma_bf16(acc2[2 * jp + 1], ah2[s], bl[2], bl[3]);
                mma_bf16(acc2[2 * jp + 1], al2[s], bh[2], bh[3]);
            }
        }

#pragma unroll
        for (int j = 0; j < 8; ++j) {
            int o0 = c * 64 + 8 * j + 2 * t;
            float2 bv = *(const float2*)(b2 + e * D_EMB + o0);
            if (aR0 >= 0) {
                float2 o;
                o.x = (acc2[j][0] + bv.x) * gv0;
                o.y = (acc2[j][1] + bv.y) * gv0;
                *(float2*)(g_part + (size_t)aR0 * D_EMB + o0) = o;
            }
            if (aR1 >= 0) {
                float2 o;
                o.x = (acc2[j][2] + bv.x) * gv1;
                o.y = (acc2[j][3] + bv.y) * gv1;
                *(float2*)(g_part + (size_t)aR1 * D_EMB + o0) = o;
            }
        }
    }
}

// ---------------- kernel C: combine (proven) -------------------------------------
__global__ void __launch_bounds__(256) k_combine(float* __restrict__ out) {
    __shared__ float red[256];
    int tid = threadIdx.x;
    size_t f4 = (size_t)blockIdx.x * 256 + tid;
    size_t t  = f4 >> 6;
    int    q  = (int)(f4 & 63);

    float4 aa = *((const float4*)(g_part + (t * 2)     * D_EMB) + q);
    float4 bb = *((const float4*)(g_part + (t * 2 + 1) * D_EMB) + q);
    float4 y;
    y.x = aa.x + bb.x; y.y = aa.y + bb.y; y.z = aa.z + bb.z; y.w = aa.w + bb.w;

    float kd = fabsf(y.x) + fabsf(y.y) + fabsf(y.z) + fabsf(y.w);

    float4 o;
    o.x = y.x * 0.5f; o.y = y.y * 0.5f; o.z = y.z * 0.5f; o.w = y.w * 0.5f;
    ((float4*)out)[f4] = o;

    red[tid] = kd;
    __syncthreads();
    for (int s = 128; s; s >>= 1) {
        if (tid < s) red[tid] += red[tid + s];
        __syncthreads();
    }
    if (tid == 0) g_kd_part[blockIdx.x] = red[0];
}

// ---------------- kernel D: finalize loss + reset counters (proven) --------------
__global__ void __launch_bounds__(256) k_final(float* __restrict__ out, int out_size) {
    __shared__ float red[256];
    __shared__ float impS[N_EXP * 256];
    int tid = threadIdx.x;

    float s = 0.f;
    for (int i = tid; i < NBLK_C; i += 256) s += g_kd_part[i];
    red[tid] = s;
    __syncthreads();
    for (int st = 128; st; st >>= 1) {
        if (tid < st) red[tid] += red[tid + st];
        __syncthreads();
    }
    float kd_total = red[0];
    __syncthreads();

    float imp[N_EXP];
#pragma unroll
    for (int e = 0; e < N_EXP; ++e) imp[e] = 0.f;
    for (int i = tid; i < NBLK_G; i += 256) {
#pragma unroll
        for (int e = 0; e < N_EXP; ++e)
            imp[e] += g_imp_part[i * N_EXP + e];
    }
#pragma unroll
    for (int e = 0; e < N_EXP; ++e) impS[e * 256 + tid] = imp[e];
    __syncthreads();
    for (int st = 128; st; st >>= 1) {
        if (tid < st)
#pragma unroll
            for (int e = 0; e < N_EXP; ++e)
                impS[e * 256 + tid] += impS[e * 256 + tid + st];
        __syncthreads();
    }

    if (tid == 0) {
        float iv[N_EXP], lv[N_EXP];
        float si = 0.f, sl = 0.f;
#pragma unroll
        for (int e = 0; e < N_EXP; ++e) {
            iv[e] = impS[e * 256];
            lv[e] = (float)g_count[e];
            si += iv[e]; sl += lv[e];
        }
        float mi = si / (float)N_EXP, ml = sl / (float)N_EXP;
        float vi = 0.f, vl = 0.f;
#pragma unroll
        for (int e = 0; e < N_EXP; ++e) {
            float di = iv[e] - mi; vi += di * di;
            float dl = lv[e] - ml; vl += dl * dl;
        }
        vi /= (float)(N_EXP - 1);
        vl /= (float)(N_EXP - 1);
        float aux = vi / (mi * mi + 1e-10f) + vl / (ml * ml + 1e-10f);
        float kd  = kd_total / (float)((size_t)T_TOK * D_EMB);
        if (out_size > T_TOK * D_EMB)
            out[(size_t)T_TOK * D_EMB] = aux + kd;
    }

    __syncthreads();
    if (tid < N_EXP) g_count[tid] = 0;
}

// ---------------- launch ----------------------------------------------------------
extern "C" void kernel_launch(void* const* d_in, const int* in_sizes, int n_in,
                              void* d_out, int out_size) {
    const float* x  = (const float*)d_in[0];
    const float* wg = (const float*)d_in[1];
    const float* w1 = (const float*)d_in[2];
    const float* b1 = (const float*)d_in[3];
    const float* w2 = (const float*)d_in[4];
    const float* b2 = (const float*)d_in[5];
    float* out = (float*)d_out;

    cudaFuncSetAttribute(k_ffn, cudaFuncAttributeMaxDynamicSharedMemorySize, SMEM_FFN);

    k_gate<<<NBLK_G, 256>>>(x, wg);
    dim3 gB(T_TOK / MTOK, N_EXP);
    k_ffn<<<gB, 256, SMEM_FFN>>>(x, w1, b1, w2, b2);
    k_combine<<<NBLK_C, 256>>>(out);
    k_final<<<1, 256>>>(out, out_size);
}

// round 17
// speedup vs baseline: 1.1809x; 1.0094x over previous
#include <cuda_runtime.h>
#include <cuda_bf16.h>
#include <math.h>
#include <stdint.h>

#define T_TOK   65536
#define D_EMB   256
#define H_DIM   64
#define N_EXP   10
#define MTOK    128
#define NBLK_C  16384
#define NBLK_G  (T_TOK / 32)

// smem element strides (bf16 elems), 4-bank shift per row
#define SA1 72             // 64 k-chunk + 8 pad
#define SB1 72
#define SA2 72
#define SB2C 136           // 128 n-chunk + 8 pad

// byte offsets in the 1024-aligned dynamic smem tile
// phase 1 (per K=64 chunk):
#define A1HI 0
#define A1LO 18432         // 128*72*2
#define B1HI 36864
#define B1LO 46080         // +64*72*2
// phase 2 (A2 reuses A1 space; B2 reuses B1 space, N-chunked):
#define A2HI 0
#define A2LO 18432
#define B2HI 36864
#define B2LO 54272         // +64*136*2
#define ASH_OFF 71680
#define GSH_OFF 72192
#define SMEM_FFN (72704 + 1024)

// ---------------- scratch ------------------------------------------------------
__device__ int   g_count[N_EXP];
__device__ int   g_bucket[N_EXP * T_TOK];
__device__ float g_gates[T_TOK * 2];
__device__ float g_part [(size_t)T_TOK * 2 * D_EMB];
__device__ float g_kd_part[NBLK_C];
__device__ float g_imp_part[NBLK_G * N_EXP];

// ---------------- helpers --------------------------------------------------------
__device__ __forceinline__ uint32_t smem_u32(const void* p) {
    uint32_t a;
    asm("{ .reg .u64 t; cvta.to.shared.u64 t, %1; cvt.u32.u64 %0, t; }" : "=r"(a) : "l"(p));
    return a;
}
__device__ __forceinline__ uint32_t bf16x2_rn(float lo, float hi) {
    uint32_t r;
    asm("cvt.rn.bf16x2.f32 %0,%1,%2;" : "=r"(r) : "f"(hi), "f"(lo));
    return r;
}
__device__ __forceinline__ void split2(float f0, float f1, uint32_t& hp, uint32_t& lp) {
    hp = bf16x2_rn(f0, f1);
    float r0 = f0 - __uint_as_float(hp << 16);
    float r1 = f1 - __uint_as_float(hp & 0xFFFF0000u);
    lp = bf16x2_rn(r0, r1);
}
__device__ __forceinline__ void sts64(uint32_t addr, uint32_t a, uint32_t b) {
    asm volatile("st.shared.v2.b32 [%0], {%1,%2};" :: "r"(addr), "r"(a), "r"(b) : "memory");
}
__device__ __forceinline__ void sts32(uint32_t addr, uint32_t v) {
    asm volatile("st.shared.b32 [%0], %1;" :: "r"(addr), "r"(v) : "memory");
}
__device__ __forceinline__ void ldm4(uint32_t* r, uint32_t a) {
    asm volatile("ldmatrix.sync.aligned.m8n8.x4.shared.b16 {%0,%1,%2,%3}, [%4];"
                 : "=r"(r[0]), "=r"(r[1]), "=r"(r[2]), "=r"(r[3]) : "r"(a));
}
__device__ __forceinline__ void ldm4t(uint32_t* r, uint32_t a) {
    asm volatile("ldmatrix.sync.aligned.m8n8.x4.trans.shared.b16 {%0,%1,%2,%3}, [%4];"
                 : "=r"(r[0]), "=r"(r[1]), "=r"(r[2]), "=r"(r[3]) : "r"(a));
}
__device__ __forceinline__ void mma_bf16(float* c, const uint32_t* a, uint32_t b0, uint32_t b1) {
    asm volatile(
        "mma.sync.aligned.m16n8k16.row.col.f32.bf16.bf16.f32 "
        "{%0,%1,%2,%3},{%4,%5,%6,%7},{%8,%9},{%0,%1,%2,%3};"
        : "+f"(c[0]), "+f"(c[1]), "+f"(c[2]), "+f"(c[3])
        : "r"(a[0]), "r"(a[1]), "r"(a[2]), "r"(a[3]), "r"(b0), "r"(b1));
}

// ---------------- kernel A: gating + importance partials (proven) ---------------
__global__ void __launch_bounds__(256) k_gate(const float* __restrict__ x,
                                              const float* __restrict__ wg) {
    __shared__ float wgs[N_EXP * D_EMB];
    __shared__ float impW[8][N_EXP];
    int tid = threadIdx.x;
    for (int i = tid; i < D_EMB * N_EXP; i += 256) {
        int e = i / D_EMB, d = i - e * D_EMB;
        wgs[i] = wg[d * N_EXP + e];
    }
    __syncthreads();

    int warp = tid >> 5, lane = tid & 31;
    int t0 = blockIdx.x * 32 + warp * 4;

    float impL[N_EXP];
#pragma unroll
    for (int e = 0; e < N_EXP; ++e) impL[e] = 0.f;

    for (int r = 0; r < 4; ++r) {
        int t = t0 + r;
        float part[N_EXP];
#pragma unroll
        for (int e = 0; e < N_EXP; ++e) part[e] = 0.f;
#pragma unroll
        for (int dd = 0; dd < 8; ++dd) {
            int d = dd * 32 + lane;
            float xv = x[(size_t)t * D_EMB + d];
#pragma unroll
            for (int e = 0; e < N_EXP; ++e)
                part[e] = fmaf(xv, wgs[e * D_EMB + d], part[e]);
        }
#pragma unroll
        for (int e = 0; e < N_EXP; ++e) {
#pragma unroll
            for (int off = 16; off; off >>= 1)
                part[e] += __shfl_xor_sync(0xffffffffu, part[e], off);
        }
        if (lane == 0) {
            float m0 = -1e30f; int e0 = 0;
#pragma unroll
            for (int e = 0; e < N_EXP; ++e) if (part[e] > m0) { m0 = part[e]; e0 = e; }
            float m1 = -1e30f; int e1 = 0;
#pragma unroll
            for (int e = 0; e < N_EXP; ++e) if (e != e0 && part[e] > m1) { m1 = part[e]; e1 = e; }
            float ex = expf(m1 - m0);
            float s  = 1.f + ex;
            float g0 = 1.f / s;
            float g1 = ex / s;
            g_gates[2 * t]     = g0;
            g_gates[2 * t + 1] = g1;
#pragma unroll
            for (int q = 0; q < N_EXP; ++q) {
                if (q == e0) impL[q] += g0;
                if (q == e1) impL[q] += g1;
            }
            int p0 = atomicAdd(&g_count[e0], 1);
            g_bucket[e0 * T_TOK + p0] = (t << 1);
            int p1 = atomicAdd(&g_count[e1], 1);
            g_bucket[e1 * T_TOK + p1] = (t << 1) | 1;
        }
    }

    if (lane == 0) {
#pragma unroll
        for (int e = 0; e < N_EXP; ++e) impW[warp][e] = impL[e];
    }
    __syncthreads();
    if (tid < N_EXP) {
        float s = 0.f;
#pragma unroll
        for (int w = 0; w < 8; ++w) s += impW[w][tid];
        g_imp_part[blockIdx.x * N_EXP + tid] = s;
    }
}

// ---------------- kernel B: mma.sync split-bf16 FFN, K=64 chunks, 3 blocks/SM ---
__global__ void __launch_bounds__(256, 3) k_ffn(const float* __restrict__ x,
                                                const float* __restrict__ w1,
                                                const float* __restrict__ b1,
                                                const float* __restrict__ w2,
                                                const float* __restrict__ b2) {
    int e = blockIdx.y;
    int n_total = g_count[e];
    int base = blockIdx.x * MTOK;
    if (base >= n_total) return;

    extern __shared__ char smraw[];
    char* bp = (char*)(((uintptr_t)smraw + 1023) & ~(uintptr_t)1023);
    uint32_t tb = smem_u32(bp);
    int*   ash = (int*)(bp + ASH_OFF);
    float* gsh = (float*)(bp + GSH_OFF);

    int tid  = threadIdx.x;
    int lane = tid & 31;
    int R    = (tid >> 5) * 16;

    if (tid < MTOK) {
        int a = (base + tid < n_total) ? g_bucket[e * T_TOK + base + tid] : -1;
        ash[tid] = a;
        gsh[tid] = (a >= 0) ? g_gates[a] : 0.f;
    }
    __syncthreads();

    // ldmatrix lane geometry
    int rowA = R + (lane & 7) + ((lane >> 3) & 1) * 8;
    int kAo  = (lane >> 4) * 8;
    int kBo  = (lane & 7) + ((lane >> 3) & 1) * 8;
    int nBo  = (lane >> 4) * 8;

    int srow  = tid >> 1;       // staging: token row
    int shalf = tid & 1;        // staging: k half (32 floats)
    int aS = ash[srow];
    const float* xrow = (aS >= 0) ? (x + (size_t)(aS >> 1) * D_EMB) : (const float*)0;

    float acc1[8][4];
#pragma unroll
    for (int j = 0; j < 8; ++j)
#pragma unroll
        for (int q = 0; q < 4; ++q) acc1[j][q] = 0.f;

    // ---- GEMM1 over four K=64 chunks ----
#pragma unroll 1
    for (int kc = 0; kc < 4; ++kc) {
        if (kc) __syncthreads();   // previous chunk fully consumed

        // stage A1 chunk: x[k = kc*64 + shalf*32 .. +32)
        {
            const float4* src = (aS >= 0)
                ? (const float4*)(xrow + kc * 64 + shalf * 32) : (const float4*)0;
            uint32_t dst = tb + A1HI + (uint32_t)srow * (SA1 * 2) + shalf * 64;
#pragma unroll 4
            for (int i = 0; i < 8; ++i) {
                float4 v = (aS >= 0) ? src[i] : make_float4(0.f, 0.f, 0.f, 0.f);
                uint32_t h0, l0, h1, l1;
                split2(v.x, v.y, h0, l0);
                split2(v.z, v.w, h1, l1);
                sts64(dst + i * 8,                 h0, h1);
                sts64(dst + i * 8 + (A1LO - A1HI), l0, l1);
            }
        }
        // stage B1 chunk: w1[k = kc*64 .. +64)[n=64]
        {
            const float4* w1g = (const float4*)(w1 + (size_t)e * D_EMB * H_DIM)
                                + kc * 1024;
#pragma unroll 2
            for (int i = tid; i < 1024; i += 256) {
                int k  = i >> 4;
                int n4 = (i & 15) * 4;
                float4 v = w1g[i];
                uint32_t h0, l0, h1, l1;
                split2(v.x, v.y, h0, l0);
                split2(v.z, v.w, h1, l1);
                uint32_t dst = tb + B1HI + ((uint32_t)(k * SB1 + n4) << 1);
                sts64(dst,                 h0, h1);
                sts64(dst + (B1LO - B1HI), l0, l1);
            }
        }
        __syncthreads();

#pragma unroll 2
        for (int s = 0; s < 4; ++s) {
            uint32_t ah[4], al[4];
            uint32_t aAddr = tb + A1HI + ((uint32_t)(rowA * SA1 + s * 16 + kAo) << 1);
            ldm4(ah, aAddr);
            ldm4(al, aAddr + (A1LO - A1HI));
#pragma unroll
            for (int jp = 0; jp < 4; ++jp) {
                uint32_t bh[4], bl[4];
                uint32_t bAddr = tb + B1HI +
                    ((uint32_t)((s * 16 + kBo) * SB1 + jp * 16 + nBo) << 1);
                ldm4t(bh, bAddr);
                ldm4t(bl, bAddr + (B1LO - B1HI));
                mma_bf16(acc1[2 * jp],     ah, bh[0], bh[1]);
                mma_bf16(acc1[2 * jp],     ah, bl[0], bl[1]);
                mma_bf16(acc1[2 * jp],     al, bh[0], bh[1]);
                mma_bf16(acc1[2 * jp + 1], ah, bh[2], bh[3]);
                mma_bf16(acc1[2 * jp + 1], ah, bl[2], bl[3]);
                mma_bf16(acc1[2 * jp + 1], al, bh[2], bh[3]);
            }
        }
    }
    __syncthreads();   // GEMM1 reads done; A1/B1 regions reused below

    // ---- epilogue1: h = relu(D1 + b1) -> A2 (split bf16) ----
    {
        int g = lane >> 2, t = lane & 3;
        int r0 = R + g, r1 = R + g + 8;
#pragma unroll
        for (int j = 0; j < 8; ++j) {
            int h0 = 8 * j + 2 * t;
            float2 bv = *(const float2*)(b1 + e * H_DIM + h0);
            float v0 = fmaxf(acc1[j][0] + bv.x, 0.f);
            float v1 = fmaxf(acc1[j][1] + bv.y, 0.f);
            float v2 = fmaxf(acc1[j][2] + bv.x, 0.f);
            float v3 = fmaxf(acc1[j][3] + bv.y, 0.f);
            uint32_t hp, lp;
            split2(v0, v1, hp, lp);
            uint32_t d0 = tb + A2HI + ((uint32_t)(r0 * SA2 + h0) << 1);
            sts32(d0, hp);
            sts32(d0 + (A2LO - A2HI), lp);
            split2(v2, v3, hp, lp);
            uint32_t d1 = tb + A2HI + ((uint32_t)(r1 * SA2 + h0) << 1);
            sts32(d1, hp);
            sts32(d1 + (A2LO - A2HI), lp);
        }
    }

    int g = lane >> 2, t = lane & 3;
    int aR0 = ash[R + g], aR1 = ash[R + g + 8];
    float gv0 = gsh[R + g], gv1 = gsh[R + g + 8];

    // ---- GEMM2 over two N=128 chunks (B2 staged per chunk) ----
#pragma unroll 1
    for (int nc = 0; nc < 2; ++nc) {
        __syncthreads();   // nc=0: A2 ready & B1 dead; nc=1: prev B2 reads done

        // stage B2 chunk: w2[k=0..64)[n = nc*128 .. +128)
        {
            const float4* w2g = (const float4*)(w2 + (size_t)e * H_DIM * D_EMB);
#pragma unroll 4
            for (int i = tid; i < 2048; i += 256) {
                int k  = i >> 5;
                int n4 = (i & 31) * 4;
                float4 v = w2g[k * 64 + nc * 32 + (i & 31)];
                uint32_t h0, l0, h1, l1;
                split2(v.x, v.y, h0, l0);
                split2(v.z, v.w, h1, l1);
                uint32_t dst = tb + B2HI + ((uint32_t)(k * SB2C + n4) << 1);
                sts64(dst,                 h0, h1);
                sts64(dst + (B2LO - B2HI), l0, l1);
            }
        }
        __syncthreads();

#pragma unroll 1
        for (int c2 = 0; c2 < 2; ++c2) {
            float acc2[8][4];
#pragma unroll
            for (int j = 0; j < 8; ++j)
#pragma unroll
                for (int q = 0; q < 4; ++q) acc2[j][q] = 0.f;

#pragma unroll
            for (int s = 0; s < 4; ++s) {
                uint32_t ah[4], al[4];
                uint32_t aAddr = tb + A2HI + ((uint32_t)(rowA * SA2 + s * 16 + kAo) << 1);
                ldm4(ah, aAddr);
                ldm4(al, aAddr + (A2LO - A2HI));
#pragma unroll
                for (int jp = 0; jp < 4; ++jp) {
                    uint32_t bh[4], bl[4];
                    uint32_t bAddr = tb + B2HI +
                        ((uint32_t)((s * 16 + kBo) * SB2C + c2 * 64 + jp * 16 + nBo) << 1);
                    ldm4t(bh, bAddr);
                    ldm4t(bl, bAddr + (B2LO - B2HI));
                    mma_bf16(acc2[2 * jp],     ah, bh[0], bh[1]);
                    mma_bf16(acc2[2 * jp],     ah, bl[0], bl[1]);
                    mma_bf16(acc2[2 * jp],     al, bh[0], bh[1]);
                    mma_bf16(acc2[2 * jp + 1], ah, bh[2], bh[3]);
                    mma_bf16(acc2[2 * jp + 1], ah, bl[2], bl[3]);
                    mma_bf16(acc2[2 * jp + 1], al, bh[2], bh[3]);
                }
            }

#pragma unroll
            for (int j = 0; j < 8; ++j) {
                int o0 = nc * 128 + c2 * 64 + 8 * j + 2 * t;
                float2 bv = *(const float2*)(b2 + e * D_EMB + o0);
                if (aR0 >= 0) {
                    float2 o;
                    o.x = (acc2[j][0] + bv.x) * gv0;
                    o.y = (acc2[j][1] + bv.y) * gv0;
                    *(float2*)(g_part + (size_t)aR0 * D_EMB + o0) = o;
                }
                if (aR1 >= 0) {
                    float2 o;
                    o.x = (acc2[j][2] + bv.x) * gv1;
                    o.y = (acc2[j][3] + bv.y) * gv1;
                    *(float2*)(g_part + (size_t)aR1 * D_EMB + o0) = o;
                }
            }
        }
    }
}

// ---------------- kernel C: combine (proven) -------------------------------------
__global__ void __launch_bounds__(256) k_combine(float* __restrict__ out) {
    __shared__ float red[256];
    int tid = threadIdx.x;
    size_t f4 = (size_t)blockIdx.x * 256 + tid;
    size_t t  = f4 >> 6;
    int    q  = (int)(f4 & 63);

    float4 aa = *((const float4*)(g_part + (t * 2)     * D_EMB) + q);
    float4 bb = *((const float4*)(g_part + (t * 2 + 1) * D_EMB) + q);
    float4 y;
    y.x = aa.x + bb.x; y.y = aa.y + bb.y; y.z = aa.z + bb.z; y.w = aa.w + bb.w;

    float kd = fabsf(y.x) + fabsf(y.y) + fabsf(y.z) + fabsf(y.w);

    float4 o;
    o.x = y.x * 0.5f; o.y = y.y * 0.5f; o.z = y.z * 0.5f; o.w = y.w * 0.5f;
    ((float4*)out)[f4] = o;

    red[tid] = kd;
    __syncthreads();
    for (int s = 128; s; s >>= 1) {
        if (tid < s) red[tid] += red[tid + s];
        __syncthreads();
    }
    if (tid == 0) g_kd_part[blockIdx.x] = red[0];
}

// ---------------- kernel D: finalize loss + reset counters (proven) --------------
__global__ void __launch_bounds__(256) k_final(float* __restrict__ out, int out_size) {
    __shared__ float red[256];
    __shared__ float impS[N_EXP * 256];
    int tid = threadIdx.x;

    float s = 0.f;
    for (int i = tid; i < NBLK_C; i += 256) s += g_kd_part[i];
    red[tid] = s;
    __syncthreads();
    for (int st = 128; st; st >>= 1) {
        if (tid < st) red[tid] += red[tid + st];
        __syncthreads();
    }
    float kd_total = red[0];
    __syncthreads();

    float imp[N_EXP];
#pragma unroll
    for (int e = 0; e < N_EXP; ++e) imp[e] = 0.f;
    for (int i = tid; i < NBLK_G; i += 256) {
#pragma unroll
        for (int e = 0; e < N_EXP; ++e)
            imp[e] += g_imp_part[i * N_EXP + e];
    }
#pragma unroll
    for (int e = 0; e < N_EXP; ++e) impS[e * 256 + tid] = imp[e];
    __syncthreads();
    for (int st = 128; st; st >>= 1) {
        if (tid < st)
#pragma unroll
            for (int e = 0; e < N_EXP; ++e)
                impS[e * 256 + tid] += impS[e * 256 + tid + st];
        __syncthreads();
    }

    if (tid == 0) {
        float iv[N_EXP], lv[N_EXP];
        float si = 0.f, sl = 0.f;
#pragma unroll
        for (int e = 0; e < N_EXP; ++e) {
            iv[e] = impS[e * 256];
            lv[e] = (float)g_count[e];
            si += iv[e]; sl += lv[e];
        }
        float mi = si / (float)N_EXP, ml = sl / (float)N_EXP;
        float vi = 0.f, vl = 0.f;
#pragma unroll
        for (int e = 0; e < N_EXP; ++e) {
            float di = iv[e] - mi; vi += di * di;
            float dl = lv[e] - ml; vl += dl * dl;
        }
        vi /= (float)(N_EXP - 1);
        vl /= (float)(N_EXP - 1);
        float aux = vi / (mi * mi + 1e-10f) + vl / (ml * ml + 1e-10f);
        float kd  = kd_total / (float)((size_t)T_TOK * D_EMB);
        if (out_size > T_TOK * D_EMB)
            out[(size_t)T_TOK * D_EMB] = aux + kd;
    }

    __syncthreads();
    if (tid < N_EXP) g_count[tid] = 0;
}

// ---------------- launch ----------------------------------------------------------
extern "C" void kernel_launch(void* const* d_in, const int* in_sizes, int n_in,
                              void* d_out, int out_size) {
    const float* x  = (const float*)d_in[0];
    const float* wg = (const float*)d_in[1];
    const float* w1 = (const float*)d_in[2];
    const float* b1 = (const float*)d_in[3];
    const float* w2 = (const float*)d_in[4];
    const float* b2 = (const float*)d_in[5];
    float* out = (float*)d_out;

    cudaFuncSetAttribute(k_ffn, cudaFuncAttributeMaxDynamicSharedMemorySize, SMEM_FFN);

    k_gate<<<NBLK_G, 256>>>(x, wg);
    dim3 gB(T_TOK / MTOK, N_EXP);
    k_ffn<<<gB, 256, SMEM_FFN>>>(x, w1, b1, w2, b2);
    k_combine<<<NBLK_C, 256>>>(out);
    k_final<<<1, 256>>>(out, out_size);
}